// round 6
// baseline (speedup 1.0000x reference)
#include <cuda_runtime.h>
#include <cstdint>

// x (8,3,1024,1024) f32 -> out (8,3,512,512) f32
// d_in: [0]=x, [1]=w0 (K0*512), [2]=fov0 (K0*512 i32)  -> dim2 (H, vertical)
//       [3]=w1 (K1*512), [4]=fov1 (K1*512 i32)         -> dim3 (W, horizontal)
//
// R6: streaming-accumulator vertical pass. Each regular block streams its
// 22 distinct input rows exactly once; each row FMAs into the (<=4) output
// accumulators whose tap window contains it (compile-time indices, no
// register shifting). All row loads are independent -> high MLP, hides the
// ~600cyc DRAM latency that bound R5 (issue was 37.6%).
// Phase 2: parity-split smem tile, conflict-free LDS (unchanged from R5).

#define BC     24
#define IN_H   1024
#define IN_W   1024
#define OUT_H  512
#define OUT_W  512
#define G      8           // output rows per block

// ---------------------------------------------------------------------------
template<int K>
__global__ __launch_bounds__(256, 5)
void fused_stream_kernel(const float* __restrict__ x,
                         const float* __restrict__ w0,
                         const int*   __restrict__ fov0,
                         const float* __restrict__ w1,
                         const int*   __restrict__ fov1,
                         float*       __restrict__ out,
                         int K1)
{
    __shared__ float tile[G][IN_W];              // 32 KB, parity-permuted

    const int t   = threadIdx.x;                 // 0..255
    const int bc  = blockIdx.y;
    const int oh0 = blockIdx.x * G;

    const float4* xb = reinterpret_cast<const float4*>(x + (size_t)bc * IN_H * IN_W);

    // ---- regularity check: fov0[j][oh0+i] == start + 2i + j, w0 oh-invariant
    const int start = fov0[oh0];
    int flag = 1;
    if (t < K * G) {
        const int j  = t / G;
        const int i  = t % G;
        const int oh = oh0 + i;
        flag  = (fov0[j * OUT_H + oh] == start + 2 * i + j);
        flag &= (w0  [j * OUT_H + oh] == w0[j * OUT_H + oh0]);
    }
    const int regular = __syncthreads_and(flag);

    if (regular) {
        // ---------- Phase 1a: stream 22 rows into G accumulators ----------
        constexpr int NROWS = K + 2 * (G - 1);   // 22 for K=8

        float wv[K];
#pragma unroll
        for (int j = 0; j < K; ++j) wv[j] = w0[j * OUT_H + oh0];

        float4 acc[G];
#pragma unroll
        for (int i = 0; i < G; ++i) { acc[i].x = acc[i].y = acc[i].z = acc[i].w = 0.f; }

#pragma unroll
        for (int m = 0; m < NROWS; ++m) {
            const float4 v = xb[(size_t)(start + m) * (IN_W / 4) + t];
#pragma unroll
            for (int i = 0; i < G; ++i) {
                const int j = m - 2 * i;          // tap index for output i
                if (j >= 0 && j < K) {            // compile-time pruned
                    acc[i].x += wv[j] * v.x;
                    acc[i].y += wv[j] * v.y;
                    acc[i].z += wv[j] * v.z;
                    acc[i].w += wv[j] * v.w;
                }
            }
            // retire accumulator i as soon as its window closes (m == 2i+K-1)
            if (m >= K - 1 && ((m - (K - 1)) & 1) == 0) {
                const int i = (m - (K - 1)) / 2;
                float2 e; e.x = acc[i].x; e.y = acc[i].z;
                float2 o; o.x = acc[i].y; o.y = acc[i].w;
                reinterpret_cast<float2*>(tile[i])[t]       = e;
                reinterpret_cast<float2*>(tile[i] + 512)[t] = o;
            }
        }
    } else {
        // ---------- Phase 1b: generic gather (boundary blocks) ----------
        for (int i = 0; i < G; ++i) {
            const int oh = oh0 + i;
            float ax = 0.f, ay = 0.f, az = 0.f, aw = 0.f;
            for (int j = 0; j < K; ++j) {
                const int   r = fov0[j * OUT_H + oh];
                const float w = w0  [j * OUT_H + oh];
                const float4 v = xb[(size_t)r * (IN_W / 4) + t];
                ax += w * v.x;
                ay += w * v.y;
                az += w * v.z;
                aw += w * v.w;
            }
            float2 e; e.x = ax; e.y = az;
            float2 o; o.x = ay; o.y = aw;
            reinterpret_cast<float2*>(tile[i])[t]       = e;
            reinterpret_cast<float2*>(tile[i] + 512)[t] = o;
        }
    }
    __syncthreads();

    // ---------------- Phase 2: horizontal resample from permuted smem -------
    float a0[G], a1[G];
#pragma unroll
    for (int i = 0; i < G; ++i) { a0[i] = 0.f; a1[i] = 0.f; }

    for (int j = 0; j < K1; ++j) {
        const float w_a = w1  [j * OUT_W + t];
        const float w_b = w1  [j * OUT_W + t + 256];
        const int   f_a = fov1[j * OUT_W + t];
        const int   f_b = fov1[j * OUT_W + t + 256];
        const int p_a = (f_a >> 1) + ((f_a & 1) << 9);
        const int p_b = (f_b >> 1) + ((f_b & 1) << 9);
#pragma unroll
        for (int i = 0; i < G; ++i) {
            a0[i] += w_a * tile[i][p_a];
            a1[i] += w_b * tile[i][p_b];
        }
    }

#pragma unroll
    for (int i = 0; i < G; ++i) {
        float* orow = out + ((size_t)bc * OUT_H + oh0 + i) * OUT_W;
        orow[t]       = a0[i];
        orow[t + 256] = a1[i];
    }
}

// ---------------------------------------------------------------------------
// Generic fallback kernel for K0 outside the template set.
__global__ __launch_bounds__(256)
void fused_generic_kernel(const float* __restrict__ x,
                          const float* __restrict__ w0,
                          const int*   __restrict__ fov0,
                          const float* __restrict__ w1,
                          const int*   __restrict__ fov1,
                          float*       __restrict__ out,
                          int K0, int K1)
{
    __shared__ float tile[G][IN_W];
    const int t   = threadIdx.x;
    const int bc  = blockIdx.y;
    const int oh0 = blockIdx.x * G;
    const float4* xb = reinterpret_cast<const float4*>(x + (size_t)bc * IN_H * IN_W);

    for (int i = 0; i < G; ++i) {
        const int oh = oh0 + i;
        float ax = 0.f, ay = 0.f, az = 0.f, aw = 0.f;
        for (int j = 0; j < K0; ++j) {
            const int   r = fov0[j * OUT_H + oh];
            const float w = w0  [j * OUT_H + oh];
            const float4 v = xb[(size_t)r * (IN_W / 4) + t];
            ax += w * v.x; ay += w * v.y; az += w * v.z; aw += w * v.w;
        }
        float2 e; e.x = ax; e.y = az;
        float2 o; o.x = ay; o.y = aw;
        reinterpret_cast<float2*>(tile[i])[t]       = e;
        reinterpret_cast<float2*>(tile[i] + 512)[t] = o;
    }
    __syncthreads();

    float a0[G], a1[G];
#pragma unroll
    for (int i = 0; i < G; ++i) { a0[i] = 0.f; a1[i] = 0.f; }
    for (int j = 0; j < K1; ++j) {
        const float w_a = w1  [j * OUT_W + t];
        const float w_b = w1  [j * OUT_W + t + 256];
        const int   f_a = fov1[j * OUT_W + t];
        const int   f_b = fov1[j * OUT_W + t + 256];
        const int p_a = (f_a >> 1) + ((f_a & 1) << 9);
        const int p_b = (f_b >> 1) + ((f_b & 1) << 9);
#pragma unroll
        for (int i = 0; i < G; ++i) {
            a0[i] += w_a * tile[i][p_a];
            a1[i] += w_b * tile[i][p_b];
        }
    }
#pragma unroll
    for (int i = 0; i < G; ++i) {
        float* orow = out + ((size_t)bc * OUT_H + oh0 + i) * OUT_W;
        orow[t]       = a0[i];
        orow[t + 256] = a1[i];
    }
}

// ---------------------------------------------------------------------------

extern "C" void kernel_launch(void* const* d_in, const int* in_sizes, int n_in,
                              void* d_out, int out_size)
{
    const float* x    = (const float*)d_in[0];
    const float* w0   = (const float*)d_in[1];
    const int*   fov0 = (const int*)  d_in[2];
    const float* w1   = (const float*)d_in[3];
    const int*   fov1 = (const int*)  d_in[4];
    float*       out  = (float*)d_out;

    const int K0 = in_sizes[1] / OUT_H;   // vertical taps
    const int K1 = in_sizes[3] / OUT_W;   // horizontal taps

    dim3 grid(OUT_H / G, BC);

    switch (K0) {
    case 6:  fused_stream_kernel< 6><<<grid, 256>>>(x, w0, fov0, w1, fov1, out, K1); break;
    case 7:  fused_stream_kernel< 7><<<grid, 256>>>(x, w0, fov0, w1, fov1, out, K1); break;
    case 8:  fused_stream_kernel< 8><<<grid, 256>>>(x, w0, fov0, w1, fov1, out, K1); break;
    case 9:  fused_stream_kernel< 9><<<grid, 256>>>(x, w0, fov0, w1, fov1, out, K1); break;
    case 10: fused_stream_kernel<10><<<grid, 256>>>(x, w0, fov0, w1, fov1, out, K1); break;
    case 11: fused_stream_kernel<11><<<grid, 256>>>(x, w0, fov0, w1, fov1, out, K1); break;
    case 12: fused_stream_kernel<12><<<grid, 256>>>(x, w0, fov0, w1, fov1, out, K1); break;
    default: fused_generic_kernel<<<grid, 256>>>(x, w0, fov0, w1, fov1, out, K0, K1); break;
    }
}